// round 7
// baseline (speedup 1.0000x reference)
#include <cuda_runtime.h>
#include <cstdint>

// x[16,256,128,128] f32, w[512,256,3,3], bias[512], blur_k[4,4] -> y[16,512,64,64]
// R7: fix separable-blur row factor (v = u, NOT 4u; K.sum()=64 so K = u u^T with u_b=k_b/8).
#define WP       68
#define NSTRIDE  8772        // 129*68
#define CSTRIDE  140352      // 16*NSTRIDE
#define PLANE    35930112    // 256*CSTRIDE

__device__ __align__(16) float g_xbs[2u * 35930112u];  // blurred, parity-split, tf32-rounded
__device__ __align__(16) float g_apk[4 * 72 * 4096];   // weights, mma-fragment order

// ---------------- helpers ----------------
__device__ __forceinline__ uint32_t smem_u32(const void* p) {
    uint32_t a;
    asm("{ .reg .u64 t; cvta.to.shared.u64 t, %1; cvt.u32.u64 %0, t; }" : "=r"(a) : "l"(p));
    return a;
}
__device__ __forceinline__ float tf32r(float x) {
    uint32_t r; asm("cvt.rna.tf32.f32 %0, %1;" : "=r"(r) : "f"(x));
    return __uint_as_float(r);
}
#define CP16(dst, src) \
    asm volatile("cp.async.cg.shared.global [%0], [%1], 16;" :: "r"(dst), "l"(src))
#define CP4(dst, src) \
    asm volatile("cp.async.ca.shared.global [%0], [%1], 4;" :: "r"(dst), "l"(src))
#define CPCOMMIT() asm volatile("cp.async.commit_group;" ::: "memory")
#define CPWAIT(n)  asm volatile("cp.async.wait_group %0;" :: "n"(n) : "memory")

__device__ __forceinline__ void mma8(float* d, const float4& a, float b0f, float b1f) {
    const uint32_t* ai = reinterpret_cast<const uint32_t*>(&a);
    uint32_t b0 = __float_as_uint(b0f), b1 = __float_as_uint(b1f);
    asm volatile(
        "mma.sync.aligned.m16n8k8.row.col.f32.tf32.tf32.f32 "
        "{%0,%1,%2,%3}, {%4,%5,%6,%7}, {%8,%9}, {%0,%1,%2,%3};"
        : "+f"(d[0]), "+f"(d[1]), "+f"(d[2]), "+f"(d[3])
        : "r"(ai[0]), "r"(ai[1]), "r"(ai[2]), "r"(ai[3]), "r"(b0), "r"(b1));
}

// ---------------- 1. weight prep: scale + tf32-round + mma-fragment permute ----
__global__ __launch_bounds__(256) void prep_kernel(const float* __restrict__ w) {
    int idx = blockIdx.x * 256 + threadIdx.x;       // 512*2304
    if (idx >= 512 * 2304) return;
    int oc = idx / 2304, k = idx - oc * 2304;       // k = tap*256 + c
    int c = k & 255, tap = k >> 8;
    int kh = tap / 3, kw = tap - kh * 3;
    float v = tf32r(w[((oc * 256 + c) * 3 + kh) * 3 + kw] * (1.0f / 48.0f));
    int mt = oc >> 7, m = oc & 127;
    int kt = k >> 5, kl = k & 31;
    int ks = kl >> 3, kc = kl & 7;
    int chi = kc >> 2, c4 = kc & 3;
    int wm = m >> 6, mi = (m >> 4) & 3, mr = m & 15;
    int rhi = mr >> 3, gid = mr & 7;
    int lanei = gid * 4 + c4;
    int comp = chi * 2 + rhi;                       // (r,c),(r+8,c),(r,c+4),(r+8,c+4)
    g_apk[(size_t)(mt * 72 + kt) * 4096 + ((ks * 8 + wm * 4 + mi) * 32 + lanei) * 4 + comp] = v;
}

// ---------------- 2. separable blur, smem-tiled, parity-split output ----------
__global__ __launch_bounds__(256) void blur_kernel(const float* __restrict__ x,
                                                   const float* __restrict__ bk) {
    __shared__ float s[37 * 140];
    int tid = threadIdx.x, bid = blockIdx.x;        // 16384 CTAs
    int hb = bid & 3, n = (bid >> 2) & 15, c = bid >> 6;
    int h0 = hb * 33;
    const float* xp = x + (size_t)(n * 256 + c) * 16384;
#pragma unroll
    for (int i = 0; i < 6; ++i) {
        int idx = tid + i * 256;
        if (idx < 37 * 35) {
            int rr = idx / 35, c4 = idx - rr * 35;
            int ih = h0 - 2 + rr;
            float4 v = make_float4(0.f, 0.f, 0.f, 0.f);
            if (ih >= 0 && ih < 128 && c4 < 32)
                v = *reinterpret_cast<const float4*>(xp + ih * 128 + c4 * 4);
            *reinterpret_cast<float4*>(&s[rr * 140 + c4 * 4]) = v;
        }
    }
    // K is exactly rank-1: K = u u^T with u_b = column sum of K (k_b/8 for [1,3,3,1]).
    // Row factor v equals u (K.sum()=64 normalization): v_a*u_b = k_a*k_b/64 = K[a][b].
    float u0 = __ldg(bk + 0) + __ldg(bk + 4) + __ldg(bk + 8)  + __ldg(bk + 12);
    float u1 = __ldg(bk + 1) + __ldg(bk + 5) + __ldg(bk + 9)  + __ldg(bk + 13);
    float u2 = __ldg(bk + 2) + __ldg(bk + 6) + __ldg(bk + 10) + __ldg(bk + 14);
    float u3 = __ldg(bk + 3) + __ldg(bk + 7) + __ldg(bk + 11) + __ldg(bk + 15);
    float v0 = u0, v1 = u1, v2 = u2, v3 = u3;
    __syncthreads();
#pragma unroll 1
    for (int t = tid; t < 561; t += 256) {          // 17 h-pairs x 33 w-quads
        int ph = t / 33, wq = t - ph * 33;
        int par = (wq >= 17) ? 1 : 0;
        int qw = par ? (wq - 17) : wq;
        int h0p = ph * 2;
        int basew = qw * 8 + par;                   // w' = basew + 2j (same parity)
        float hv[5][4];
#pragma unroll
        for (int dr = 0; dr < 5; ++dr) {
            const float* row = s + (h0p + dr) * 140;
            float xv[10];
#pragma unroll
            for (int q = 0; q < 10; ++q) {
                int iw = basew - 2 + q;
                xv[q] = (iw >= 0) ? row[iw] : 0.0f; // cols >=128 are zero-padded
            }
#pragma unroll
            for (int jj = 0; jj < 4; ++jj)
                hv[dr][jj] = u0 * xv[2 * jj] + u1 * xv[2 * jj + 1]
                           + u2 * xv[2 * jj + 2] + u3 * xv[2 * jj + 3];
        }
#pragma unroll
        for (int hh = 0; hh < 2; ++hh) {
            int hp = h0p + hh, habs = h0 + hp;
            if (hp > 32 || habs > 128) continue;
            float o[4];
#pragma unroll
            for (int jj = 0; jj < 4; ++jj)
                o[jj] = tf32r(v0 * hv[hh][jj] + v1 * hv[hh + 1][jj]
                            + v2 * hv[hh + 2][jj] + v3 * hv[hh + 3][jj]);
            float* dst = g_xbs + (size_t)par * PLANE + (size_t)c * CSTRIDE
                       + (size_t)n * NSTRIDE + (size_t)habs * WP + qw * 4;
            if (par == 0 && qw == 16) dst[0] = o[0];            // w'=128 only
            else *reinterpret_cast<float4*>(dst) = make_float4(o[0], o[1], o[2], o[3]);
        }
    }
}

// ---------------- 3. implicit GEMM 128x128, K-tile 32, 3-stage cp.async -------
#define STG_STRIDE 33792u    // 16384 (A) + 17408 (B: 32 x 136 floats)

__device__ __forceinline__ void load_stage(uint32_t sbase, int kt, int tid, int mt,
                                           int n_img, int ohbase) {
    const float* asrc = g_apk + (size_t)(mt * 72 + kt) * 4096;
#pragma unroll
    for (int i = 0; i < 4; ++i)
        CP16(sbase + (uint32_t)(tid + 256 * i) * 16u, asrc + (tid + 256 * i) * 4);
    int tap = kt >> 3, ct = kt & 7;
    int kh = tap / 3, kw = tap - kh * 3;
    int par = kw & 1, add = kw >> 1;
    int j = tid & 127, kb = (tid >> 7) << 4;
    int oh = ohbase + (j >> 6), ow = j & 63;
    const float* src = g_xbs + (size_t)par * PLANE + (size_t)(ct * 32 + kb) * CSTRIDE
                     + (size_t)n_img * NSTRIDE + (size_t)(2 * oh + kh) * WP + add + ow;
    uint32_t sB = sbase + 16384u + (uint32_t)(kb * 136 + j) * 4u;
#pragma unroll
    for (int i = 0; i < 16; ++i)
        CP4(sB + (uint32_t)(i * 136 * 4), src + (size_t)i * CSTRIDE);
}

__device__ __forceinline__ void mma_stage(const char* base, int lane, int wm, int wn,
                                          float acc[4][4][4]) {
    const float4* sA4 = reinterpret_cast<const float4*>(base);
    const float*  sB  = reinterpret_cast<const float*>(base + 16384);
    int r = lane & 3, gid = lane >> 2;
#pragma unroll
    for (int ks = 0; ks < 4; ++ks) {
        float4 af[4];
#pragma unroll
        for (int mi = 0; mi < 4; ++mi)
            af[mi] = sA4[(ks * 8 + wm * 4 + mi) * 32 + lane];
        float b0[4], b1[4];
#pragma unroll
        for (int ni = 0; ni < 4; ++ni) {
            int nn = wn * 32 + ni * 8 + gid;
            b0[ni] = sB[(ks * 8 + r) * 136 + nn];
            b1[ni] = sB[(ks * 8 + 4 + r) * 136 + nn];
        }
#pragma unroll
        for (int mi = 0; mi < 4; ++mi)
#pragma unroll
            for (int ni = 0; ni < 4; ++ni)
                mma8(acc[mi][ni], af[mi], b0[ni], b1[ni]);
    }
}

__global__ __launch_bounds__(256, 2) void gemm_kernel(const float* __restrict__ bias,
                                                      float* __restrict__ out) {
    extern __shared__ char smem[];
    uint32_t sbu = smem_u32(smem);
    const int tid = threadIdx.x, lane = tid & 31, wid = tid >> 5;
    const int wm = wid >> 2, wn = wid & 3;
    const int bid = blockIdx.x;                     // 2048 CTAs
    const int mt = bid & 3, nt = bid >> 2;          // 4 mt share B via L2
    const int n_img = nt >> 5, ohbase = (nt & 31) << 1;

    float acc[4][4][4];
#pragma unroll
    for (int a = 0; a < 4; ++a)
#pragma unroll
        for (int b = 0; b < 4; ++b)
#pragma unroll
            for (int q = 0; q < 4; ++q) acc[a][b][q] = 0.0f;

    load_stage(sbu, 0, tid, mt, n_img, ohbase);               CPCOMMIT();
    load_stage(sbu + STG_STRIDE, 1, tid, mt, n_img, ohbase);  CPCOMMIT();

#pragma unroll 1
    for (int kt = 0; kt < 72; ++kt) {
        CPWAIT(1);
        __syncthreads();
        if (kt + 2 < 72)
            load_stage(sbu + (uint32_t)((kt + 2) % 3) * STG_STRIDE, kt + 2,
                       tid, mt, n_img, ohbase);
        CPCOMMIT();
        mma_stage(smem + (size_t)(kt % 3) * STG_STRIDE, lane, wm, wn, acc);
    }

    // epilogue: D frag (row gid/+8, cols 2*tig,2*tig+1) -> float2 stores
#pragma unroll
    for (int mi = 0; mi < 4; ++mi) {
        int m = wm * 64 + mi * 16 + (lane >> 2);
        float blo = __ldg(bias + mt * 128 + m);
        float bhi = __ldg(bias + mt * 128 + m + 8);
#pragma unroll
        for (int ni = 0; ni < 4; ++ni) {
            int jj = wn * 32 + ni * 8 + (lane & 3) * 2;
            int oh = ohbase + (jj >> 6), ow = jj & 63;
            size_t base = (((size_t)n_img * 512 + mt * 128 + m) * 64 + oh) * 64 + ow;
            *reinterpret_cast<float2*>(out + base) =
                make_float2(acc[mi][ni][0] + blo, acc[mi][ni][1] + blo);
            *reinterpret_cast<float2*>(out + base + 8 * 4096) =
                make_float2(acc[mi][ni][2] + bhi, acc[mi][ni][3] + bhi);
        }
    }
}

// ---------------- launch ----------------
extern "C" void kernel_launch(void* const* d_in, const int* in_sizes, int n_in,
                              void* d_out, int out_size) {
    const float* x    = (const float*)d_in[0];
    const float* w    = (const float*)d_in[1];
    const float* bias = (const float*)d_in[2];
    const float* bk   = (const float*)d_in[3];
    float* out = (float*)d_out;
    (void)in_sizes; (void)n_in; (void)out_size;

    cudaFuncSetAttribute(gemm_kernel, cudaFuncAttributeMaxDynamicSharedMemorySize, 101376);

    prep_kernel<<<4608, 256>>>(w);
    blur_kernel<<<16384, 256>>>(x, bk);
    gemm_kernel<<<2048, 256, 101376>>>(bias, out);
}